// round 2
// baseline (speedup 1.0000x reference)
#include <cuda_runtime.h>
#include <cstdint>
#include <math.h>

// Problem constants (fixed by the dataset)
#define BTOT 128
#define HDIM 128
#define ADIM 384            // 3*H
#define MT   64             // edges per CTA tile
#define NTHREADS 256        // 8 warps

// SMEM strides (floats), chosen for conflict-free m16n8k8 fragment loads
#define TOK_STRIDE 132      // token tiles [64][128] padded
#define X_STRIDE   388      // X1/X2 [64][384] padded
#define WS_STRIDE  136      // weight k-chunk [32][128] padded

// SMEM layout (in floats)
//  X1      : 64*388          = 24832
//  R2      : 3*64*132        = 25344   (token tiles, later overlaid by X2 [64][388] = 24832)
//  ws      : 32*136          =  4352
//  b1s     : 384
//  b2s     : 384
//  score_s : 64
//  eb_s    : 64 (ints)
// total 55424 floats = 221696 bytes (< 227 KB sm_100a per-block limit)
#define SM_X1     0
#define SM_R2     (SM_X1 + MT * X_STRIDE)
#define SM_WS     (SM_R2 + 3 * MT * TOK_STRIDE)
#define SM_B1     (SM_WS + 32 * WS_STRIDE)
#define SM_B2     (SM_B1 + ADIM)
#define SM_SCORE  (SM_B2 + ADIM)
#define SM_EB     (SM_SCORE + MT)
#define SM_FLOATS (SM_EB + MT)
#define SMEM_BYTES (SM_FLOATS * 4)

// fp32 query scratch (no cudaMalloc allowed; __device__ global is the sanctioned path)
__device__ float g_query[BTOT * ADIM];

__device__ __forceinline__ unsigned f2tf(float x) {
    unsigned r;
    asm("cvt.rna.tf32.f32 %0, %1;" : "=r"(r) : "f"(x));
    return r;
}
__device__ __forceinline__ float f2tff(float x) { return __uint_as_float(f2tf(x)); }

__device__ __forceinline__ float gelu_exact(float x) {
    return 0.5f * x * (1.0f + erff(x * 0.7071067811865476f));
}

// mma.sync m16n8k8 tf32: D = A(16x8, row) * B(8x8, col) + C
__device__ __forceinline__ void mma_tf32(float* c, const unsigned* a, const unsigned* b) {
    asm volatile(
        "mma.sync.aligned.m16n8k8.row.col.f32.tf32.tf32.f32 "
        "{%0,%1,%2,%3}, {%4,%5,%6,%7}, {%8,%9}, {%0,%1,%2,%3};"
        : "+f"(c[0]), "+f"(c[1]), "+f"(c[2]), "+f"(c[3])
        : "r"(a[0]), "r"(a[1]), "r"(a[2]), "r"(a[3]), "r"(b[0]), "r"(b[1]));
}

// ---------------------------------------------------------------------------
// Kernel 1: query = hidden @ Wq, exact fp32.  grid=(128), block=(384)
// ---------------------------------------------------------------------------
__global__ void query_kernel(const float* __restrict__ hidden,
                             const float* __restrict__ Wq) {
    __shared__ float hrow[HDIM];
    const int b = blockIdx.x;
    const int a = threadIdx.x;
    if (a < HDIM) hrow[a] = hidden[b * HDIM + a];
    __syncthreads();
    float s = 0.f;
    #pragma unroll 8
    for (int h = 0; h < HDIM; h++) s += hrow[h] * Wq[h * ADIM + a];
    g_query[b * ADIM + a] = s;
}

// ---------------------------------------------------------------------------
// Fused main kernel: per-CTA tile of 64 edges, 3 GEMM stages + dot epilogue.
// Warp tiling: 8 warps in a 2x4 grid over a [64 x 128] output chunk;
// each warp owns a 32x32 sub-tile = 2 m-tiles x 4 n-tiles of m16n8k8.
// ---------------------------------------------------------------------------
template <int K>
__device__ __forceinline__ void gemm_stage(
    float acc[2][4][4],
    const float* __restrict__ A_sm, int a_stride,
    const float* __restrict__ Wg, int w_rowlen, int w_coloff,
    float* __restrict__ ws,
    int tid, int m_off, int n_off, int group, int t4)
{
    #pragma unroll
    for (int mt = 0; mt < 2; mt++)
        #pragma unroll
        for (int nt = 0; nt < 4; nt++)
            #pragma unroll
            for (int i = 0; i < 4; i++) acc[mt][nt][i] = 0.f;

    for (int k0 = 0; k0 < K; k0 += 32) {
        __syncthreads();   // previous consumers of ws (and producers of A_sm) done
        // cooperative stage of W[k0:k0+32, w_coloff:w_coloff+128] -> ws (tf32-rounded)
        for (int i = tid; i < 32 * 32; i += NTHREADS) {
            const int r = i >> 5, c4 = i & 31;
            const float4 v = *(const float4*)(Wg + (long)(k0 + r) * w_rowlen + w_coloff + c4 * 4);
            float* d = ws + r * WS_STRIDE + c4 * 4;
            d[0] = f2tff(v.x); d[1] = f2tff(v.y); d[2] = f2tff(v.z); d[3] = f2tff(v.w);
        }
        __syncthreads();

        #pragma unroll
        for (int kk = 0; kk < 4; kk++) {
            const int kb = kk * 8;
            unsigned afr[2][4];
            #pragma unroll
            for (int mt = 0; mt < 2; mt++) {
                const int r0 = m_off + mt * 16 + group;
                const float* ap = A_sm + (long)r0 * a_stride + k0 + kb + t4;
                afr[mt][0] = __float_as_uint(ap[0]);
                afr[mt][1] = __float_as_uint(ap[8 * a_stride]);
                afr[mt][2] = __float_as_uint(ap[4]);
                afr[mt][3] = __float_as_uint(ap[8 * a_stride + 4]);
            }
            unsigned bfr[4][2];
            #pragma unroll
            for (int nt = 0; nt < 4; nt++) {
                const int nc = n_off + nt * 8 + group;
                const float* bp = ws + (kb + t4) * WS_STRIDE + nc;
                bfr[nt][0] = __float_as_uint(bp[0]);
                bfr[nt][1] = __float_as_uint(bp[4 * WS_STRIDE]);
            }
            #pragma unroll
            for (int mt = 0; mt < 2; mt++)
                #pragma unroll
                for (int nt = 0; nt < 4; nt++)
                    mma_tf32(acc[mt][nt], afr[mt], bfr[nt]);
        }
    }
}

__global__ void __launch_bounds__(NTHREADS, 1)
fused_kernel(const float* __restrict__ rel, const float* __restrict__ nod,
             const float* __restrict__ hed, const int* __restrict__ edge_batch,
             const float* __restrict__ Wr, const float* __restrict__ Wn,
             const float* __restrict__ Wh,
             const float* __restrict__ W1, const float* __restrict__ b1,
             const float* __restrict__ W2, const float* __restrict__ b2,
             float* __restrict__ out)
{
    extern __shared__ float sm[];
    float* X1      = sm + SM_X1;
    float* R2      = sm + SM_R2;     // tokens, later X2
    float* ws      = sm + SM_WS;
    float* b1s     = sm + SM_B1;
    float* b2s     = sm + SM_B2;
    float* score_s = sm + SM_SCORE;
    int*   eb_s    = (int*)(sm + SM_EB);

    const int tid   = threadIdx.x;
    const int lane  = tid & 31;
    const int warp  = tid >> 5;
    const int group = lane >> 2;
    const int t4    = lane & 3;
    const int m_off = (warp >> 2) * 32;   // 0 or 32
    const int n_off = (warp & 3) * 32;    // 0..96
    const long e0   = (long)blockIdx.x * MT;

    if (tid < MT) {
        eb_s[tid] = edge_batch[e0 + tid];
        score_s[tid] = 0.f;
    }
    for (int i = tid; i < ADIM; i += NTHREADS) { b1s[i] = b1[i]; b2s[i] = b2[i]; }

    // Load 3 token tiles [64][128] into R2 (tf32-rounded), coalesced float4
    for (int i = tid; i < 3 * MT * 32; i += NTHREADS) {
        const int t   = i / (MT * 32);
        const int rem = i - t * (MT * 32);
        const int r   = rem >> 5;
        const int c4  = rem & 31;
        const float* src = (t == 0) ? rel : ((t == 1) ? nod : hed);
        const float4 v = *(const float4*)(src + (e0 + r) * HDIM + c4 * 4);
        float* d = R2 + t * MT * TOK_STRIDE + r * TOK_STRIDE + c4 * 4;
        d[0] = f2tff(v.x); d[1] = f2tff(v.y); d[2] = f2tff(v.z); d[3] = f2tff(v.w);
    }
    // (first gemm_stage __syncthreads covers all the stores above)

    // ---------------- Stage 1: X1 = [rel@Wr | node@Wn | head@Wh] ----------------
    for (int nb = 0; nb < 3; nb++) {
        const float* tokA = R2 + nb * MT * TOK_STRIDE;
        const float* Wg   = (nb == 0) ? Wr : ((nb == 1) ? Wn : Wh);
        float acc[2][4][4];
        gemm_stage<HDIM>(acc, tokA, TOK_STRIDE, Wg, HDIM, 0, ws, tid, m_off, n_off, group, t4);
        #pragma unroll
        for (int mt = 0; mt < 2; mt++) {
            const int r0 = m_off + mt * 16 + group;
            #pragma unroll
            for (int nt = 0; nt < 4; nt++) {
                const int c0 = nb * 128 + n_off + nt * 8 + 2 * t4;
                X1[(long)r0 * X_STRIDE + c0]           = f2tff(acc[mt][nt][0]);
                X1[(long)r0 * X_STRIDE + c0 + 1]       = f2tff(acc[mt][nt][1]);
                X1[(long)(r0 + 8) * X_STRIDE + c0]     = f2tff(acc[mt][nt][2]);
                X1[(long)(r0 + 8) * X_STRIDE + c0 + 1] = f2tff(acc[mt][nt][3]);
            }
        }
    }

    // ---------------- Stage 2: X2 = gelu(X1 @ W1 + b1) (X2 overlays tokens) ----
    for (int nb = 0; nb < 3; nb++) {
        float acc[2][4][4];
        gemm_stage<ADIM>(acc, X1, X_STRIDE, W1, ADIM, nb * 128, ws, tid, m_off, n_off, group, t4);
        #pragma unroll
        for (int mt = 0; mt < 2; mt++) {
            const int r0 = m_off + mt * 16 + group;
            #pragma unroll
            for (int nt = 0; nt < 4; nt++) {
                const int c0 = nb * 128 + n_off + nt * 8 + 2 * t4;
                const float bb0 = b1s[c0], bb1 = b1s[c0 + 1];
                R2[(long)r0 * X_STRIDE + c0]           = f2tff(gelu_exact(acc[mt][nt][0] + bb0));
                R2[(long)r0 * X_STRIDE + c0 + 1]       = f2tff(gelu_exact(acc[mt][nt][1] + bb1));
                R2[(long)(r0 + 8) * X_STRIDE + c0]     = f2tff(gelu_exact(acc[mt][nt][2] + bb0));
                R2[(long)(r0 + 8) * X_STRIDE + c0 + 1] = f2tff(gelu_exact(acc[mt][nt][3] + bb1));
            }
        }
    }

    // ---------------- Stage 3: Y = X2 @ W2 + b2; scores = dot(Y, q[eb]) --------
    for (int nb = 0; nb < 3; nb++) {
        float acc[2][4][4];
        gemm_stage<ADIM>(acc, R2, X_STRIDE, W2, ADIM, nb * 128, ws, tid, m_off, n_off, group, t4);
        #pragma unroll
        for (int mt = 0; mt < 2; mt++) {
            const int r0  = m_off + mt * 16 + group;
            const int ebA = eb_s[r0];
            const int ebB = eb_s[r0 + 8];
            float pA = 0.f, pB = 0.f;
            #pragma unroll
            for (int nt = 0; nt < 4; nt++) {
                const int c0 = nb * 128 + n_off + nt * 8 + 2 * t4;
                const float2 qa = *(const float2*)(g_query + (long)ebA * ADIM + c0);
                const float2 qb = *(const float2*)(g_query + (long)ebB * ADIM + c0);
                const float bb0 = b2s[c0], bb1 = b2s[c0 + 1];
                pA += (acc[mt][nt][0] + bb0) * qa.x + (acc[mt][nt][1] + bb1) * qa.y;
                pB += (acc[mt][nt][2] + bb0) * qb.x + (acc[mt][nt][3] + bb1) * qb.y;
            }
            // reduce across the 4 lanes of the quad (t4 = 0..3)
            pA += __shfl_xor_sync(0xffffffffu, pA, 1);
            pA += __shfl_xor_sync(0xffffffffu, pA, 2);
            pB += __shfl_xor_sync(0xffffffffu, pB, 1);
            pB += __shfl_xor_sync(0xffffffffu, pB, 2);
            if (t4 == 0) {
                atomicAdd(&score_s[r0], pA);
                atomicAdd(&score_s[r0 + 8], pB);
            }
        }
    }

    __syncthreads();
    if (tid < MT) out[e0 + tid] = score_s[tid];
}

// ---------------------------------------------------------------------------
extern "C" void kernel_launch(void* const* d_in, const int* in_sizes, int n_in,
                              void* d_out, int out_size) {
    const float* hidden = (const float*)d_in[0];
    const float* rel    = (const float*)d_in[1];
    const float* nod    = (const float*)d_in[2];
    const float* hed    = (const float*)d_in[3];
    const int*   eb     = (const int*)d_in[4];
    // d_in[5] = edge_ptr : unused by the reference
    const float* Wq     = (const float*)d_in[6];
    const float* Wr     = (const float*)d_in[7];
    const float* Wn     = (const float*)d_in[8];
    const float* Wh     = (const float*)d_in[9];
    const float* W1     = (const float*)d_in[10];
    const float* b1     = (const float*)d_in[11];
    const float* W2     = (const float*)d_in[12];
    const float* b2     = (const float*)d_in[13];
    float* out = (float*)d_out;

    const int E = in_sizes[4];          // 262144, divisible by MT
    const int nblocks = E / MT;

    query_kernel<<<BTOT, ADIM>>>(hidden, Wq);

    cudaFuncSetAttribute(fused_kernel, cudaFuncAttributeMaxDynamicSharedMemorySize,
                         SMEM_BYTES);
    fused_kernel<<<nblocks, NTHREADS, SMEM_BYTES>>>(
        rel, nod, hed, eb, Wr, Wn, Wh, W1, b1, W2, b2, out);
}

// round 3
// speedup vs baseline: 4.2645x; 4.2645x over previous
#include <cuda_runtime.h>
#include <cstdint>
#include <math.h>

// Problem constants (fixed by the dataset)
#define BTOT 128
#define HDIM 128
#define ADIM 384            // 3*H
#define MT   64             // edges per CTA tile
#define NTHREADS 256        // 8 warps
#define NCHUNKS 36          // 3 n-chunks x 12 k-chunks
#define A_STRIDE 36         // A chunk [64][32] padded
#define W_STRIDE 136        // W chunk [32][128] padded
#define A_SZ (MT * A_STRIDE)     // 2304
#define W_SZ (32 * W_STRIDE)     // 4352

// SMEM: 2*A_SZ + 2*W_SZ + b1(384) + score(64) + eb(64) = 13824 floats = 55296 B
#define SM_A     0
#define SM_W     (SM_A + 2 * A_SZ)
#define SM_B1    (SM_W + 2 * W_SZ)
#define SM_SCORE (SM_B1 + ADIM)
#define SM_EB    (SM_SCORE + MT)
#define SM_FLOATS (SM_EB + MT)
#define SMEM_BYTES (SM_FLOATS * 4)

// __device__ scratch (no cudaMalloc allowed)
__device__ float g_query[BTOT * ADIM];   // q[b][a] fp32 exact
__device__ float g_qT[ADIM * BTOT];      // q transposed [a][b]
__device__ float g_z[BTOT * ADIM];       // z[b][k] = sum_n W2[k][n] q[b][n], fp32 exact
__device__ float g_cb[BTOT];             // cb[b] = b2 . q[b]
__device__ float g_C[ADIM * ADIM];       // C[k][n] = fused stage1+2 weight, tf32-rounded

__device__ __forceinline__ unsigned f2tf(float x) {
    unsigned r;
    asm("cvt.rna.tf32.f32 %0, %1;" : "=r"(r) : "f"(x));
    return r;
}
__device__ __forceinline__ float f2tff(float x) { return __uint_as_float(f2tf(x)); }

__device__ __forceinline__ float gelu_exact(float x) {
    return 0.5f * x * (1.0f + erff(x * 0.7071067811865476f));
}

// mma.sync m16n8k8 tf32: D = A(16x8, row) * B(8x8, col) + C  (validated in R2)
__device__ __forceinline__ void mma_tf32(float* c, const unsigned* a, const unsigned* b) {
    asm volatile(
        "mma.sync.aligned.m16n8k8.row.col.f32.tf32.tf32.f32 "
        "{%0,%1,%2,%3}, {%4,%5,%6,%7}, {%8,%9}, {%0,%1,%2,%3};"
        : "+f"(c[0]), "+f"(c[1]), "+f"(c[2]), "+f"(c[3])
        : "r"(a[0]), "r"(a[1]), "r"(a[2]), "r"(a[3]), "r"(b[0]), "r"(b[1]));
}

// ---------------------------------------------------------------------------
// Prep 1: q = hidden @ Wq (exact fp32) + transposed copy. grid=(128) block=(384)
// ---------------------------------------------------------------------------
__global__ void query_kernel(const float* __restrict__ hidden,
                             const float* __restrict__ Wq) {
    __shared__ float hrow[HDIM];
    const int b = blockIdx.x;
    const int a = threadIdx.x;
    if (a < HDIM) hrow[a] = hidden[b * HDIM + a];
    __syncthreads();
    float s = 0.f;
    #pragma unroll 8
    for (int h = 0; h < HDIM; h++) s += hrow[h] * Wq[h * ADIM + a];
    g_query[b * ADIM + a] = s;
    g_qT[a * BTOT + b] = s;
}

// ---------------------------------------------------------------------------
// Prep 2: z[b][k] = sum_n W2[k][n] * q[b][n]  (exact fp32). grid=(384) block=(128)
// ---------------------------------------------------------------------------
__global__ void z_kernel(const float* __restrict__ W2) {
    __shared__ float wrow[ADIM];
    const int k = blockIdx.x;
    const int b = threadIdx.x;
    for (int i = b; i < ADIM; i += 128) wrow[i] = W2[k * ADIM + i];
    __syncthreads();
    float s = 0.f;
    #pragma unroll 8
    for (int n = 0; n < ADIM; n++) s += wrow[n] * g_qT[n * BTOT + b];
    g_z[b * ADIM + k] = s;
}

// ---------------------------------------------------------------------------
// Prep 3: cb[b] = b2 . q[b]. grid=(128) block=(384)
// ---------------------------------------------------------------------------
__global__ void cb_kernel(const float* __restrict__ b2) {
    __shared__ float red[12];
    const int b = blockIdx.x;
    const int t = threadIdx.x;
    float v = b2[t] * g_query[b * ADIM + t];
    #pragma unroll
    for (int o = 16; o > 0; o >>= 1) v += __shfl_down_sync(0xffffffffu, v, o);
    if ((t & 31) == 0) red[t >> 5] = v;
    __syncthreads();
    if (t == 0) {
        float s = 0.f;
        #pragma unroll
        for (int i = 0; i < 12; i++) s += red[i];
        g_cb[b] = s;
    }
}

// ---------------------------------------------------------------------------
// Prep 4: C[kg][n] = sum_h W_t[d][h] * W1[t*128+h][n], tf32-rounded.
// kg = t*128+d. grid=(384) block=(384)
// ---------------------------------------------------------------------------
__global__ void c_kernel(const float* __restrict__ Wr, const float* __restrict__ Wn,
                         const float* __restrict__ Wh, const float* __restrict__ W1) {
    __shared__ float wrow[HDIM];
    const int kg = blockIdx.x;
    const int n  = threadIdx.x;
    const int t  = kg >> 7;
    const int d  = kg & 127;
    const float* Wt = (t == 0) ? Wr : ((t == 1) ? Wn : Wh);
    if (n < HDIM) wrow[n] = Wt[d * HDIM + n];
    __syncthreads();
    float s = 0.f;
    #pragma unroll 8
    for (int h = 0; h < HDIM; h++) s += wrow[h] * W1[(t * HDIM + h) * ADIM + n];
    g_C[kg * ADIM + n] = f2tff(s);
}

// ---------------------------------------------------------------------------
// Main fused kernel: scores = gelu([rel|node|head] @ C + b1) . z[eb] + cb[eb]
// One [64 x 384] x [384-K] GEMM per CTA, N processed in 3 chunks of 128.
// 8 warps in 2x4 grid over [64 x 128]; warp tile 32x32 (2 m x 4 n m16n8k8).
// Double-buffered A/W chunk staging, one __syncthreads per chunk.
// ---------------------------------------------------------------------------
__global__ void __launch_bounds__(NTHREADS, 2)
fused_kernel(const float* __restrict__ rel, const float* __restrict__ nod,
             const float* __restrict__ hed, const int* __restrict__ edge_batch,
             const float* __restrict__ b1, float* __restrict__ out)
{
    extern __shared__ float sm[];
    float* Ab      = sm + SM_A;
    float* Wb      = sm + SM_W;
    float* b1s     = sm + SM_B1;
    float* score_s = sm + SM_SCORE;
    int*   eb_s    = (int*)(sm + SM_EB);

    const int tid   = threadIdx.x;
    const int lane  = tid & 31;
    const int warp  = tid >> 5;
    const int group = lane >> 2;
    const int t4    = lane & 3;
    const int m_off = (warp >> 2) * 32;   // 0 or 32
    const int n_off = (warp & 3) * 32;    // 0..96
    const long e0   = (long)blockIdx.x * MT;

    if (tid < MT) {
        eb_s[tid] = edge_batch[e0 + tid];
        score_s[tid] = 0.f;
    }
    for (int i = tid; i < ADIM; i += NTHREADS) b1s[i] = b1[i];

    float acc[2][4][4];
    #pragma unroll
    for (int mt = 0; mt < 2; mt++)
        #pragma unroll
        for (int nt = 0; nt < 4; nt++)
            #pragma unroll
            for (int i = 0; i < 4; i++) acc[mt][nt][i] = 0.f;

    // staging registers (double buffer pipeline)
    float4 aReg[2];
    float4 wReg[4];

    // ---- chunk m -> (nc = m/12, kc = m%12); k0 = kc*32; token t = k0>>7 ----
    // A chunk load: idx = tid + 256*j, r = idx>>3, c4 = idx&7  (2 float4/thread)
    // W chunk load: idx = tid + 256*j, r = idx>>5, c4 = idx&31 (4 float4/thread)
    {   // prologue: LDG chunk 0 (nc=0, k0=0, token=rel)
        #pragma unroll
        for (int j = 0; j < 2; j++) {
            const int idx = tid + NTHREADS * j;
            aReg[j] = *(const float4*)(rel + (e0 + (idx >> 3)) * HDIM + (idx & 7) * 4);
        }
        #pragma unroll
        for (int j = 0; j < 4; j++) {
            const int idx = tid + NTHREADS * j;
            wReg[j] = *(const float4*)(g_C + (long)(idx >> 5) * ADIM + (idx & 31) * 4);
        }
    }

    for (int m = 0; m < NCHUNKS; m++) {
        const int buf = m & 1;
        const int kc  = m - (m / 12) * 12;
        const int nc  = m / 12;

        // STS chunk m (A with tf32 rounding; W pre-rounded)
        {
            float* As = Ab + buf * A_SZ;
            float* Ws = Wb + buf * W_SZ;
            #pragma unroll
            for (int j = 0; j < 2; j++) {
                const int idx = tid + NTHREADS * j;
                float* d = As + (idx >> 3) * A_STRIDE + (idx & 7) * 4;
                d[0] = f2tff(aReg[j].x); d[1] = f2tff(aReg[j].y);
                d[2] = f2tff(aReg[j].z); d[3] = f2tff(aReg[j].w);
            }
            #pragma unroll
            for (int j = 0; j < 4; j++) {
                const int idx = tid + NTHREADS * j;
                *(float4*)(Ws + (idx >> 5) * W_STRIDE + (idx & 31) * 4) = wReg[j];
            }
        }
        __syncthreads();

        // LDG chunk m+1 (overlaps MMA below)
        if (m + 1 < NCHUNKS) {
            const int m1  = m + 1;
            const int nc1 = m1 / 12;
            const int k0  = (m1 - nc1 * 12) * 32;
            const int tt  = k0 >> 7;
            const int col0 = k0 & 127;
            const float* src = (tt == 0) ? rel : ((tt == 1) ? nod : hed);
            #pragma unroll
            for (int j = 0; j < 2; j++) {
                const int idx = tid + NTHREADS * j;
                aReg[j] = *(const float4*)(src + (e0 + (idx >> 3)) * HDIM + col0 + (idx & 7) * 4);
            }
            #pragma unroll
            for (int j = 0; j < 4; j++) {
                const int idx = tid + NTHREADS * j;
                wReg[j] = *(const float4*)(g_C + (long)(k0 + (idx >> 5)) * ADIM
                                           + nc1 * 128 + (idx & 31) * 4);
            }
        }

        // MMA over chunk m
        {
            const float* As = Ab + buf * A_SZ;
            const float* Ws = Wb + buf * W_SZ;
            #pragma unroll
            for (int kk = 0; kk < 4; kk++) {
                const int kb = kk * 8;
                unsigned afr[2][4];
                #pragma unroll
                for (int mt = 0; mt < 2; mt++) {
                    const int r0 = m_off + mt * 16 + group;
                    const float* ap = As + r0 * A_STRIDE + kb + t4;
                    afr[mt][0] = __float_as_uint(ap[0]);
                    afr[mt][1] = __float_as_uint(ap[8 * A_STRIDE]);
                    afr[mt][2] = __float_as_uint(ap[4]);
                    afr[mt][3] = __float_as_uint(ap[8 * A_STRIDE + 4]);
                }
                unsigned bfr[4][2];
                #pragma unroll
                for (int nt = 0; nt < 4; nt++) {
                    const int ncc = n_off + nt * 8 + group;
                    const float* bp = Ws + (kb + t4) * W_STRIDE + ncc;
                    bfr[nt][0] = __float_as_uint(bp[0]);
                    bfr[nt][1] = __float_as_uint(bp[4 * W_STRIDE]);
                }
                #pragma unroll
                for (int mt = 0; mt < 2; mt++)
                    #pragma unroll
                    for (int nt = 0; nt < 4; nt++)
                        mma_tf32(acc[mt][nt], afr[mt], bfr[nt]);
            }
        }

        // epilogue at the end of each n-chunk: gelu + dot with z[eb]
        if (kc == 11) {
            #pragma unroll
            for (int mt = 0; mt < 2; mt++) {
                const int r0  = m_off + mt * 16 + group;
                const int ebA = eb_s[r0];
                const int ebB = eb_s[r0 + 8];
                float pA = 0.f, pB = 0.f;
                #pragma unroll
                for (int nt = 0; nt < 4; nt++) {
                    const int c0 = nc * 128 + n_off + nt * 8 + 2 * t4;
                    const float bb0 = b1s[c0], bb1 = b1s[c0 + 1];
                    const float2 zA = *(const float2*)(g_z + (long)ebA * ADIM + c0);
                    const float2 zB = *(const float2*)(g_z + (long)ebB * ADIM + c0);
                    pA += gelu_exact(acc[mt][nt][0] + bb0) * zA.x
                        + gelu_exact(acc[mt][nt][1] + bb1) * zA.y;
                    pB += gelu_exact(acc[mt][nt][2] + bb0) * zB.x
                        + gelu_exact(acc[mt][nt][3] + bb1) * zB.y;
                    acc[mt][nt][0] = 0.f; acc[mt][nt][1] = 0.f;
                    acc[mt][nt][2] = 0.f; acc[mt][nt][3] = 0.f;
                }
                pA += __shfl_xor_sync(0xffffffffu, pA, 1);
                pA += __shfl_xor_sync(0xffffffffu, pA, 2);
                pB += __shfl_xor_sync(0xffffffffu, pB, 1);
                pB += __shfl_xor_sync(0xffffffffu, pB, 2);
                if (t4 == 0) {
                    atomicAdd(&score_s[r0], pA);
                    atomicAdd(&score_s[r0 + 8], pB);
                }
            }
        }
    }

    __syncthreads();
    if (tid < MT) out[e0 + tid] = score_s[tid] + g_cb[eb_s[tid]];
}

// ---------------------------------------------------------------------------
extern "C" void kernel_launch(void* const* d_in, const int* in_sizes, int n_in,
                              void* d_out, int out_size) {
    const float* hidden = (const float*)d_in[0];
    const float* rel    = (const float*)d_in[1];
    const float* nod    = (const float*)d_in[2];
    const float* hed    = (const float*)d_in[3];
    const int*   eb     = (const int*)d_in[4];
    // d_in[5] = edge_ptr : unused by the reference
    const float* Wq     = (const float*)d_in[6];
    const float* Wr     = (const float*)d_in[7];
    const float* Wn     = (const float*)d_in[8];
    const float* Wh     = (const float*)d_in[9];
    const float* W1     = (const float*)d_in[10];
    const float* b1     = (const float*)d_in[11];
    const float* W2     = (const float*)d_in[12];
    const float* b2     = (const float*)d_in[13];
    float* out = (float*)d_out;

    const int E = in_sizes[4];          // 262144, divisible by MT
    const int nblocks = E / MT;

    query_kernel<<<BTOT, ADIM>>>(hidden, Wq);
    z_kernel<<<ADIM, 128>>>(W2);
    cb_kernel<<<BTOT, ADIM>>>(b2);
    c_kernel<<<ADIM, ADIM>>>(Wr, Wn, Wh, W1);

    cudaFuncSetAttribute(fused_kernel, cudaFuncAttributeMaxDynamicSharedMemorySize,
                         SMEM_BYTES);
    fused_kernel<<<nblocks, NTHREADS, SMEM_BYTES>>>(rel, nod, hed, eb, b1, out);
}

// round 5
// speedup vs baseline: 5.5695x; 1.3060x over previous
#include <cuda_runtime.h>
#include <cstdint>
#include <math.h>

// Problem constants
#define BTOT 128
#define HDIM 128
#define ADIM 384
#define MT   128            // edges per CTA tile
#define NTHREADS 256        // 8 warps
#define NCHUNKS 36          // 3 n-chunks x 12 k-chunks (k=32 each)
#define NSTAGE 3

#define A_STRIDE 36         // A chunk [128][32] padded (floats)
#define W_STRIDE 136        // W chunk [32][128] padded (floats)
#define A_SZ (MT * A_STRIDE)     // 4608
#define W_SZ (32 * W_STRIDE)     // 4352

// SMEM (floats): 3*A_SZ + 3*W_SZ + b1(384) + score(128) + eb(128)
#define SM_A     0
#define SM_W     (SM_A + NSTAGE * A_SZ)
#define SM_B1    (SM_W + NSTAGE * W_SZ)
#define SM_SCORE (SM_B1 + ADIM)
#define SM_EB    (SM_SCORE + MT)
#define SM_FLOATS (SM_EB + MT)
#define SMEM_BYTES (SM_FLOATS * 4)     // 110080 B -> 2 CTAs/SM

// device scratch (no cudaMalloc allowed)
__device__ float g_query[BTOT * ADIM];
__device__ float g_qT[ADIM * BTOT];
__device__ float g_z[BTOT * ADIM];
__device__ float g_cb[BTOT];
__device__ __align__(16) float g_C[ADIM * ADIM];   // fused weight, tf32-rounded fp32

__device__ __forceinline__ unsigned f2tf(float x) {
    unsigned r;
    asm("cvt.rna.tf32.f32 %0, %1;" : "=r"(r) : "f"(x));
    return r;
}
__device__ __forceinline__ float f2tff(float x) { return __uint_as_float(f2tf(x)); }

__device__ __forceinline__ float gelu_exact(float x) {
    return 0.5f * x * (1.0f + erff(x * 0.7071067811865476f));
}

__device__ __forceinline__ void mma_tf32(float* c, const unsigned* a, const unsigned* b) {
    asm volatile(
        "mma.sync.aligned.m16n8k8.row.col.f32.tf32.tf32.f32 "
        "{%0,%1,%2,%3}, {%4,%5,%6,%7}, {%8,%9}, {%0,%1,%2,%3};"
        : "+f"(c[0]), "+f"(c[1]), "+f"(c[2]), "+f"(c[3])
        : "r"(a[0]), "r"(a[1]), "r"(a[2]), "r"(a[3]), "r"(b[0]), "r"(b[1]));
}

__device__ __forceinline__ void cp16(uint32_t smem_dst, const void* gsrc) {
    asm volatile("cp.async.cg.shared.global [%0], [%1], 16;"
                 :: "r"(smem_dst), "l"(__cvta_generic_to_global(gsrc)) : "memory");
}
__device__ __forceinline__ void cp_commit() {
    asm volatile("cp.async.commit_group;" ::: "memory");
}
template <int N>
__device__ __forceinline__ void cp_wait() {
    asm volatile("cp.async.wait_group %0;" :: "n"(N) : "memory");
}
__device__ __forceinline__ uint32_t smem_u32(const void* p) {
    uint32_t a;
    asm("{ .reg .u64 t; cvta.to.shared.u64 t, %1; cvt.u32.u64 %0, t; }" : "=r"(a) : "l"(p));
    return a;
}

// ---------------------------------------------------------------------------
// Prep kernels (validated in R3; exact fp32 math)
// ---------------------------------------------------------------------------
__global__ void query_kernel(const float* __restrict__ hidden, const float* __restrict__ Wq) {
    __shared__ float hrow[HDIM];
    const int b = blockIdx.x, a = threadIdx.x;
    if (a < HDIM) hrow[a] = hidden[b * HDIM + a];
    __syncthreads();
    float s = 0.f;
    #pragma unroll 8
    for (int h = 0; h < HDIM; h++) s += hrow[h] * Wq[h * ADIM + a];
    g_query[b * ADIM + a] = s;
    g_qT[a * BTOT + b] = s;
}

__global__ void z_kernel(const float* __restrict__ W2) {
    __shared__ float wrow[ADIM];
    const int k = blockIdx.x, b = threadIdx.x;
    for (int i = b; i < ADIM; i += 128) wrow[i] = W2[k * ADIM + i];
    __syncthreads();
    float s = 0.f;
    #pragma unroll 8
    for (int n = 0; n < ADIM; n++) s += wrow[n] * g_qT[n * BTOT + b];
    g_z[b * ADIM + k] = s;
}

__global__ void cb_kernel(const float* __restrict__ b2) {
    __shared__ float red[12];
    const int b = blockIdx.x, t = threadIdx.x;
    float v = b2[t] * g_query[b * ADIM + t];
    #pragma unroll
    for (int o = 16; o > 0; o >>= 1) v += __shfl_down_sync(0xffffffffu, v, o);
    if ((t & 31) == 0) red[t >> 5] = v;
    __syncthreads();
    if (t == 0) {
        float s = 0.f;
        #pragma unroll
        for (int i = 0; i < 12; i++) s += red[i];
        g_cb[b] = s;
    }
}

// C = blockdiag(Wr,Wn,Wh) @ W1, exact fp32, stored tf32-rounded (rna)
__global__ void c_kernel(const float* __restrict__ Wr, const float* __restrict__ Wn,
                         const float* __restrict__ Wh, const float* __restrict__ W1) {
    __shared__ float wrow[HDIM];
    const int kg = blockIdx.x, n = threadIdx.x;
    const int t = kg >> 7, d = kg & 127;
    const float* Wt = (t == 0) ? Wr : ((t == 1) ? Wn : Wh);
    if (n < HDIM) wrow[n] = Wt[d * HDIM + n];
    __syncthreads();
    float s = 0.f;
    #pragma unroll 8
    for (int h = 0; h < HDIM; h++) s += wrow[h] * W1[(t * HDIM + h) * ADIM + n];
    g_C[kg * ADIM + n] = f2tff(s);
}

// ---------------------------------------------------------------------------
// Main fused kernel: G = X @ C (tf32 mma, cp.async 3-stage pipeline)
// scores = gelu(G + b1) . z[eb] + cb[eb]
// Warp tiling: 8 warps in 2x4 over [128 x 128]; warp tile 64x32
// (4 m-tiles x 4 n-tiles of m16n8k8). acc[4][4][4] = 64 regs.
// ---------------------------------------------------------------------------
__global__ void __launch_bounds__(NTHREADS, 2)
fused_kernel(const float* __restrict__ rel, const float* __restrict__ nod,
             const float* __restrict__ hed, const int* __restrict__ edge_batch,
             const float* __restrict__ b1, float* __restrict__ out)
{
    extern __shared__ float sm[];
    float* Ab      = sm + SM_A;
    float* Wb      = sm + SM_W;
    float* b1s     = sm + SM_B1;
    float* score_s = sm + SM_SCORE;
    int*   eb_s    = (int*)(sm + SM_EB);

    const int tid   = threadIdx.x;
    const int lane  = tid & 31;
    const int warp  = tid >> 5;
    const int group = lane >> 2;
    const int t4    = lane & 3;
    const int m_off = (warp >> 2) * 64;   // 0 or 64
    const int n_off = (warp & 3) * 32;    // 0..96
    const long e0   = (long)blockIdx.x * MT;

    if (tid < MT) {
        eb_s[tid] = edge_batch[e0 + tid];
        score_s[tid] = 0.f;
    }
    for (int i = tid; i < ADIM; i += NTHREADS) b1s[i] = b1[i];

    // per-thread cp.async addressing
    const uint32_t sA = smem_u32(Ab);
    const uint32_t sW = smem_u32(Wb);

    // issue chunk m into buffer (m % 3): A 4x16B + W 4x16B per thread
    auto issue_chunk = [&](int m) {
        const int buf = m % NSTAGE;
        const int nc  = m / 12;
        const int k0  = (m - nc * 12) * 32;
        const int tt  = k0 >> 7;
        const int col0 = k0 & 127;
        const float* asrc = (tt == 0) ? rel : ((tt == 1) ? nod : hed);
        const uint32_t aBase = sA + buf * (A_SZ * 4);
        const uint32_t wBase = sW + buf * (W_SZ * 4);
        #pragma unroll
        for (int j = 0; j < 4; j++) {
            const int idx = tid + NTHREADS * j;
            const int r = idx >> 3, c = idx & 7;      // A: row 0..127, 8x16B per row
            cp16(aBase + (r * A_STRIDE + c * 4) * 4,
                 asrc + (e0 + r) * HDIM + col0 + c * 4);
        }
        #pragma unroll
        for (int j = 0; j < 4; j++) {
            const int idx = tid + NTHREADS * j;
            const int r = idx >> 5, c = idx & 31;     // W: row 0..31, 32x16B per row
            cp16(wBase + (r * W_STRIDE + c * 4) * 4,
                 g_C + (long)(k0 + r) * ADIM + nc * 128 + c * 4);
        }
        cp_commit();
    };

    float acc[4][4][4];
    #pragma unroll
    for (int mt = 0; mt < 4; mt++)
        #pragma unroll
        for (int nt = 0; nt < 4; nt++)
            #pragma unroll
            for (int i = 0; i < 4; i++) acc[mt][nt][i] = 0.f;

    issue_chunk(0);
    issue_chunk(1);

    for (int m = 0; m < NCHUNKS; m++) {
        const int buf = m % NSTAGE;
        const int kc  = m - (m / 12) * 12;
        const int nc  = m / 12;

        cp_wait<1>();        // chunk m resident
        __syncthreads();     // visible to all warps (also protects buffer reuse)

        // ---- MMA over chunk m ----
        {
            const float* As = Ab + buf * A_SZ;
            const float* Ws = Wb + buf * W_SZ;
            #pragma unroll
            for (int kk = 0; kk < 4; kk++) {
                const int kb = kk * 8;
                unsigned afr[4][4];
                #pragma unroll
                for (int mt = 0; mt < 4; mt++) {
                    const int r0 = m_off + mt * 16 + group;
                    const float* ap = As + r0 * A_STRIDE + kb + t4;
                    afr[mt][0] = __float_as_uint(ap[0]);
                    afr[mt][1] = __float_as_uint(ap[8 * A_STRIDE]);
                    afr[mt][2] = __float_as_uint(ap[4]);
                    afr[mt][3] = __float_as_uint(ap[8 * A_STRIDE + 4]);
                }
                unsigned bfr[4][2];
                #pragma unroll
                for (int nt = 0; nt < 4; nt++) {
                    const int ncc = n_off + nt * 8 + group;
                    const float* bp = Ws + (kb + t4) * W_STRIDE + ncc;
                    bfr[nt][0] = __float_as_uint(bp[0]);
                    bfr[nt][1] = __float_as_uint(bp[4 * W_STRIDE]);
                }
                #pragma unroll
                for (int mt = 0; mt < 4; mt++)
                    #pragma unroll
                    for (int nt = 0; nt < 4; nt++)
                        mma_tf32(acc[mt][nt], afr[mt], bfr[nt]);
            }
        }

        // ---- epilogue at end of each n-chunk: gelu + dot with z[eb] ----
        if (kc == 11) {
            #pragma unroll
            for (int mt = 0; mt < 4; mt++) {
                const int r0  = m_off + mt * 16 + group;
                const int ebA = eb_s[r0];
                const int ebB = eb_s[r0 + 8];
                float pA = 0.f, pB = 0.f;
                #pragma unroll
                for (int nt = 0; nt < 4; nt++) {
                    const int c0 = nc * 128 + n_off + nt * 8 + 2 * t4;
                    const float bb0 = b1s[c0], bb1 = b1s[c0 + 1];
                    const float2 zA = *(const float2*)(g_z + (long)ebA * ADIM + c0);
                    const float2 zB = *(const float2*)(g_z + (long)ebB * ADIM + c0);
                    pA += gelu_exact(acc[mt][nt][0] + bb0) * zA.x
                        + gelu_exact(acc[mt][nt][1] + bb1) * zA.y;
                    pB += gelu_exact(acc[mt][nt][2] + bb0) * zB.x
                        + gelu_exact(acc[mt][nt][3] + bb1) * zB.y;
                    acc[mt][nt][0] = 0.f; acc[mt][nt][1] = 0.f;
                    acc[mt][nt][2] = 0.f; acc[mt][nt][3] = 0.f;
                }
                pA += __shfl_xor_sync(0xffffffffu, pA, 1);
                pA += __shfl_xor_sync(0xffffffffu, pA, 2);
                pB += __shfl_xor_sync(0xffffffffu, pB, 1);
                pB += __shfl_xor_sync(0xffffffffu, pB, 2);
                if (t4 == 0) {
                    atomicAdd(&score_s[r0], pA);
                    atomicAdd(&score_s[r0 + 8], pB);
                }
            }
        }

        // ---- prefetch chunk m+2 (buffer (m+2)%3 = (m-1)%3, safe post-sync) ----
        if (m + 2 < NCHUNKS) issue_chunk(m + 2);
    }

    __syncthreads();
    if (tid < MT) out[e0 + tid] = score_s[tid] + g_cb[eb_s[tid]];
}

// ---------------------------------------------------------------------------
extern "C" void kernel_launch(void* const* d_in, const int* in_sizes, int n_in,
                              void* d_out, int out_size) {
    const float* hidden = (const float*)d_in[0];
    const float* rel    = (const float*)d_in[1];
    const float* nod    = (const float*)d_in[2];
    const float* hed    = (const float*)d_in[3];
    const int*   eb     = (const int*)d_in[4];
    // d_in[5] = edge_ptr : unused by the reference
    const float* Wq     = (const float*)d_in[6];
    const float* Wr     = (const float*)d_in[7];
    const float* Wn     = (const float*)d_in[8];
    const float* Wh     = (const float*)d_in[9];
    const float* W1     = (const float*)d_in[10];
    const float* b1     = (const float*)d_in[11];
    const float* W2     = (const float*)d_in[12];
    const float* b2     = (const float*)d_in[13];
    float* out = (float*)d_out;

    const int E = in_sizes[4];          // 262144 = 2048 * 128
    const int nblocks = E / MT;

    query_kernel<<<BTOT, ADIM>>>(hidden, Wq);
    z_kernel<<<ADIM, 128>>>(W2);
    cb_kernel<<<BTOT, ADIM>>>(b2);
    c_kernel<<<ADIM, ADIM>>>(Wr, Wn, Wh, W1);

    cudaFuncSetAttribute(fused_kernel, cudaFuncAttributeMaxDynamicSharedMemorySize,
                         SMEM_BYTES);
    fused_kernel<<<nblocks, NTHREADS, SMEM_BYTES>>>(rel, nod, hed, eb, b1, out);
}

// round 6
// speedup vs baseline: 6.8833x; 1.2359x over previous
#include <cuda_runtime.h>
#include <cuda_fp16.h>
#include <cstdint>
#include <math.h>

// Problem constants
#define BTOT 128
#define HDIM 128
#define ADIM 384
#define MT   64             // edges per CTA tile
#define NTHREADS 256        // 8 warps
#define NCHUNKS 36          // 3 n-chunks x 12 k-chunks (k=32 each)

#define A_STRH 40           // A chunk [64][32] halves, padded stride
#define W_STRH 40           // W chunk [128 n][32 k] halves, padded stride
#define A_CH (MT * A_STRH)       // 2560 halves per buffer
#define W_CH (128 * W_STRH)      // 5120 halves per buffer

// SMEM bytes: A 2 bufs + W 3 bufs + b1 + score + eb = 43008 B -> 3 CTAs/SM
#define SMEM_BYTES (2 * A_CH * 2 + 3 * W_CH * 2 + ADIM * 4 + MT * 4 + MT * 4)

// device scratch (no cudaMalloc allowed)
__device__ float g_query[BTOT * ADIM];
__device__ float g_qT[ADIM * BTOT];
__device__ float g_z[BTOT * ADIM];
__device__ float g_cb[BTOT];
__device__ __align__(16) __half g_CT[ADIM * ADIM];  // fused weight fp16, [n][k] layout

__device__ __forceinline__ float gelu_exact(float x) {
    return 0.5f * x * (1.0f + erff(x * 0.7071067811865476f));
}

// mma.sync m16n8k16 fp16: D(f32) += A(16x16 f16, row) * B(16x8 f16, col)
__device__ __forceinline__ void mma_f16(float* c, const unsigned* a, const unsigned* b) {
    asm volatile(
        "mma.sync.aligned.m16n8k16.row.col.f32.f16.f16.f32 "
        "{%0,%1,%2,%3}, {%4,%5,%6,%7}, {%8,%9}, {%0,%1,%2,%3};"
        : "+f"(c[0]), "+f"(c[1]), "+f"(c[2]), "+f"(c[3])
        : "r"(a[0]), "r"(a[1]), "r"(a[2]), "r"(a[3]), "r"(b[0]), "r"(b[1]));
}

__device__ __forceinline__ void cp16(uint32_t smem_dst, const void* gsrc) {
    asm volatile("cp.async.cg.shared.global [%0], [%1], 16;"
                 :: "r"(smem_dst), "l"(__cvta_generic_to_global(gsrc)) : "memory");
}
__device__ __forceinline__ void cp_commit() {
    asm volatile("cp.async.commit_group;" ::: "memory");
}
template <int N>
__device__ __forceinline__ void cp_wait() {
    asm volatile("cp.async.wait_group %0;" :: "n"(N) : "memory");
}
__device__ __forceinline__ uint32_t smem_u32(const void* p) {
    uint32_t a;
    asm("{ .reg .u64 t; cvta.to.shared.u64 t, %1; cvt.u32.u64 %0, t; }" : "=r"(a) : "l"(p));
    return a;
}
__device__ __forceinline__ uint32_t pk_h2(float a, float b) {
    __half2 t = __floats2half2_rn(a, b);   // a -> low half
    return *(uint32_t*)&t;
}

// ---------------------------------------------------------------------------
// Prep kernels (exact fp32 math, validated since R3)
// ---------------------------------------------------------------------------
__global__ void query_kernel(const float* __restrict__ hidden, const float* __restrict__ Wq) {
    __shared__ float hrow[HDIM];
    const int b = blockIdx.x, a = threadIdx.x;
    if (a < HDIM) hrow[a] = hidden[b * HDIM + a];
    __syncthreads();
    float s = 0.f;
    #pragma unroll 8
    for (int h = 0; h < HDIM; h++) s += hrow[h] * Wq[h * ADIM + a];
    g_query[b * ADIM + a] = s;
    g_qT[a * BTOT + b] = s;
}

__global__ void z_kernel(const float* __restrict__ W2) {
    __shared__ float wrow[ADIM];
    const int k = blockIdx.x, b = threadIdx.x;
    for (int i = b; i < ADIM; i += 128) wrow[i] = W2[k * ADIM + i];
    __syncthreads();
    float s = 0.f;
    #pragma unroll 8
    for (int n = 0; n < ADIM; n++) s += wrow[n] * g_qT[n * BTOT + b];
    g_z[b * ADIM + k] = s;
}

__global__ void cb_kernel(const float* __restrict__ b2) {
    __shared__ float red[12];
    const int b = blockIdx.x, t = threadIdx.x;
    float v = b2[t] * g_query[b * ADIM + t];
    #pragma unroll
    for (int o = 16; o > 0; o >>= 1) v += __shfl_down_sync(0xffffffffu, v, o);
    if ((t & 31) == 0) red[t >> 5] = v;
    __syncthreads();
    if (t == 0) {
        float s = 0.f;
        #pragma unroll
        for (int i = 0; i < 12; i++) s += red[i];
        g_cb[b] = s;
    }
}

// C = blockdiag(Wr,Wn,Wh) @ W1, exact fp32, stored fp16 TRANSPOSED [n][k]
__global__ void c_kernel(const float* __restrict__ Wr, const float* __restrict__ Wn,
                         const float* __restrict__ Wh, const float* __restrict__ W1) {
    __shared__ float wrow[HDIM];
    const int kg = blockIdx.x, n = threadIdx.x;
    const int t = kg >> 7, d = kg & 127;
    const float* Wt = (t == 0) ? Wr : ((t == 1) ? Wn : Wh);
    if (n < HDIM) wrow[n] = Wt[d * HDIM + n];
    __syncthreads();
    float s = 0.f;
    #pragma unroll 8
    for (int h = 0; h < HDIM; h++) s += wrow[h] * W1[(t * HDIM + h) * ADIM + n];
    g_CT[n * ADIM + kg] = __float2half_rn(s);
}

// ---------------------------------------------------------------------------
// Main fused kernel: G = X @ C via fp16 m16n8k16; scores = gelu(G+b1).z[eb]+cb[eb]
// 8 warps in 2x4 over [64 x 128]; warp tile 32x32 (2m x 4n). acc 32 regs.
// A: register-lookahead LDG fp32 -> cvt fp16 -> STS (double buffer).
// W: fp16 cp.async 3-stage from transposed g_CT.
// ---------------------------------------------------------------------------
__global__ void __launch_bounds__(NTHREADS, 3)
fused_kernel(const float* __restrict__ rel, const float* __restrict__ nod,
             const float* __restrict__ hed, const int* __restrict__ edge_batch,
             const float* __restrict__ b1, float* __restrict__ out)
{
    extern __shared__ char smem[];
    __half* Asm    = (__half*)smem;                       // 2 * A_CH
    __half* Wsm    = Asm + 2 * A_CH;                      // 3 * W_CH
    float*  b1s    = (float*)(Wsm + 3 * W_CH);
    float*  score_s = b1s + ADIM;
    int*    eb_s   = (int*)(score_s + MT);

    const int tid   = threadIdx.x;
    const int lane  = tid & 31;
    const int warp  = tid >> 5;
    const int group = lane >> 2;
    const int t4    = lane & 3;
    const int m_off = (warp >> 2) * 32;   // 0 or 32
    const int n_off = (warp & 3) * 32;    // 0..96
    const long e0   = (long)blockIdx.x * MT;

    if (tid < MT) {
        eb_s[tid] = edge_batch[e0 + tid];
        score_s[tid] = 0.f;
    }
    for (int i = tid; i < ADIM; i += NTHREADS) b1s[i] = b1[i];

    const uint32_t sW = smem_u32(Wsm);

    // W chunk m -> buffer m%3 : 128 rows x 4 x 16B, 2 cp16/thread
    auto issue_W = [&](int m) {
        const int nc = m / 12;
        const int k0 = (m - nc * 12) * 32;
        const uint32_t base = sW + (m % 3) * (W_CH * 2);
        #pragma unroll
        for (int j = 0; j < 2; j++) {
            const int idx = tid + NTHREADS * j;
            const int n = idx >> 2, c = idx & 3;
            cp16(base + (n * W_STRH + c * 8) * 2,
                 g_CT + (long)(nc * 128 + n) * ADIM + k0 + c * 8);
        }
        cp_commit();
    };

    // A chunk lookahead: 8 floats/thread (row r = tid>>2, seg s = tid&3)
    const int arow = tid >> 2, aseg = tid & 3;
    float4 aReg[2];
    auto ldg_A = [&](int m) {
        const int nc = m / 12;
        const int k0 = (m - nc * 12) * 32;
        const int tt = k0 >> 7, col0 = k0 & 127;
        const float* src = (tt == 0) ? rel : ((tt == 1) ? nod : hed);
        const float* p = src + (e0 + arow) * HDIM + col0 + aseg * 8;
        aReg[0] = *(const float4*)(p);
        aReg[1] = *(const float4*)(p + 4);
    };

    float acc[2][4][4];
    #pragma unroll
    for (int mt = 0; mt < 2; mt++)
        #pragma unroll
        for (int nt = 0; nt < 4; nt++)
            #pragma unroll
            for (int i = 0; i < 4; i++) acc[mt][nt][i] = 0.f;

    ldg_A(0);
    issue_W(0);
    issue_W(1);

    for (int m = 0; m < NCHUNKS; m++) {
        const int bufA = m & 1;
        const int bufW = m % 3;
        const int kc   = m - (m / 12) * 12;
        const int nc   = m / 12;

        // STS A chunk m (fp32 regs -> fp16 SMEM)
        {
            uint4 v;
            v.x = pk_h2(aReg[0].x, aReg[0].y);
            v.y = pk_h2(aReg[0].z, aReg[0].w);
            v.z = pk_h2(aReg[1].x, aReg[1].y);
            v.w = pk_h2(aReg[1].z, aReg[1].w);
            *(uint4*)(Asm + bufA * A_CH + arow * A_STRH + aseg * 8) = v;
        }
        cp_wait<1>();        // W chunk m resident
        __syncthreads();     // A STS visible; previous chunk fully consumed

        if (m + 1 < NCHUNKS) ldg_A(m + 1);
        if (m + 2 < NCHUNKS) issue_W(m + 2);

        // ---- MMA over chunk m: 2 k16-steps ----
        {
            const __half* As = Asm + bufA * A_CH;
            const __half* Ws = Wsm + bufW * W_CH;
            #pragma unroll
            for (int ks = 0; ks < 2; ks++) {
                const int kb = ks * 16;
                unsigned afr[2][4];
                #pragma unroll
                for (int mt = 0; mt < 2; mt++) {
                    const int r0 = m_off + mt * 16 + group;
                    const __half* ap = As + r0 * A_STRH + kb + 2 * t4;
                    afr[mt][0] = *(const unsigned*)(ap);
                    afr[mt][1] = *(const unsigned*)(ap + 8 * A_STRH);
                    afr[mt][2] = *(const unsigned*)(ap + 8);
                    afr[mt][3] = *(const unsigned*)(ap + 8 * A_STRH + 8);
                }
                unsigned bfr[4][2];
                #pragma unroll
                for (int nt = 0; nt < 4; nt++) {
                    const __half* bp = Ws + (n_off + nt * 8 + group) * W_STRH + kb + 2 * t4;
                    bfr[nt][0] = *(const unsigned*)(bp);
                    bfr[nt][1] = *(const unsigned*)(bp + 8);
                }
                #pragma unroll
                for (int mt = 0; mt < 2; mt++)
                    #pragma unroll
                    for (int nt = 0; nt < 4; nt++)
                        mma_f16(acc[mt][nt], afr[mt], bfr[nt]);
            }
        }

        // ---- epilogue at end of each n-chunk: gelu + dot with z[eb] ----
        if (kc == 11) {
            #pragma unroll
            for (int mt = 0; mt < 2; mt++) {
                const int r0  = m_off + mt * 16 + group;
                const int ebA = eb_s[r0];
                const int ebB = eb_s[r0 + 8];
                float pA = 0.f, pB = 0.f;
                #pragma unroll
                for (int nt = 0; nt < 4; nt++) {
                    const int c0 = nc * 128 + n_off + nt * 8 + 2 * t4;
                    const float bb0 = b1s[c0], bb1 = b1s[c0 + 1];
                    const float2 zA = *(const float2*)(g_z + (long)ebA * ADIM + c0);
                    const float2 zB = *(const float2*)(g_z + (long)ebB * ADIM + c0);
                    pA += gelu_exact(acc[mt][nt][0] + bb0) * zA.x
                        + gelu_exact(acc[mt][nt][1] + bb1) * zA.y;
                    pB += gelu_exact(acc[mt][nt][2] + bb0) * zB.x
                        + gelu_exact(acc[mt][nt][3] + bb1) * zB.y;
                    acc[mt][nt][0] = 0.f; acc[mt][nt][1] = 0.f;
                    acc[mt][nt][2] = 0.f; acc[mt][nt][3] = 0.f;
                }
                pA += __shfl_xor_sync(0xffffffffu, pA, 1);
                pA += __shfl_xor_sync(0xffffffffu, pA, 2);
                pB += __shfl_xor_sync(0xffffffffu, pB, 1);
                pB += __shfl_xor_sync(0xffffffffu, pB, 2);
                if (t4 == 0) {
                    atomicAdd(&score_s[r0], pA);
                    atomicAdd(&score_s[r0 + 8], pB);
                }
            }
        }
    }

    __syncthreads();
    if (tid < MT) out[e0 + tid] = score_s[tid] + g_cb[eb_s[tid]];
}

// ---------------------------------------------------------------------------
extern "C" void kernel_launch(void* const* d_in, const int* in_sizes, int n_in,
                              void* d_out, int out_size) {
    const float* hidden = (const float*)d_in[0];
    const float* rel    = (const float*)d_in[1];
    const float* nod    = (const float*)d_in[2];
    const float* hed    = (const float*)d_in[3];
    const int*   eb     = (const int*)d_in[4];
    // d_in[5] = edge_ptr : unused by the reference
    const float* Wq     = (const float*)d_in[6];
    const float* Wr     = (const float*)d_in[7];
    const float* Wn     = (const float*)d_in[8];
    const float* Wh     = (const float*)d_in[9];
    const float* W1     = (const float*)d_in[10];
    const float* b1     = (const float*)d_in[11];
    const float* W2     = (const float*)d_in[12];
    const float* b2     = (const float*)d_in[13];
    float* out = (float*)d_out;

    const int E = in_sizes[4];          // 262144 = 4096 * 64
    const int nblocks = E / MT;

    query_kernel<<<BTOT, ADIM>>>(hidden, Wq);
    z_kernel<<<ADIM, 128>>>(W2);
    cb_kernel<<<BTOT, ADIM>>>(b2);
    c_kernel<<<ADIM, ADIM>>>(Wr, Wn, Wh, W1);

    cudaFuncSetAttribute(fused_kernel, cudaFuncAttributeMaxDynamicSharedMemorySize,
                         SMEM_BYTES);
    fused_kernel<<<nblocks, NTHREADS, SMEM_BYTES>>>(rel, nod, hed, eb, b1, out);
}